// round 15
// baseline (speedup 1.0000x reference)
#include <cuda_runtime.h>
#include <cuda.h>
#include <cstdint>

#define M_TOK 4096
#define H_DIM 4096
#define F_DIM 11008

static __device__ __align__(1024) int8_t g_x8[(size_t)M_TOK * H_DIM];
static __device__ __align__(1024) int8_t g_wg8[(size_t)F_DIM * H_DIM];
static __device__ __align__(1024) int8_t g_wu8[(size_t)F_DIM * H_DIM];
static __device__ __align__(1024) int8_t g_wd8[(size_t)H_DIM * F_DIM];
static __device__ __align__(1024) int8_t g_g8[(size_t)M_TOK * F_DIM];
static __device__ __align__(1024) int8_t g_prod8[(size_t)M_TOK * F_DIM];

// ---------------- pack kernels ----------------
__global__ void __launch_bounds__(256) k_pack_xg(
    const int4* __restrict__ sX, const int4* __restrict__ sG,
    uint32_t* __restrict__ dX, uint32_t* __restrict__ dG, int n4x, int n4w)
{
    int i = (blockIdx.x * 256 + threadIdx.x) * 2;
    #pragma unroll
    for (int r = 0; r < 2; r++, i++) {
        const int4* src; uint32_t* dst; int off;
        if (i < n4x)            { src = sX; dst = dX; off = i; }
        else if (i < n4x + n4w) { src = sG; dst = dG; off = i - n4x; }
        else break;
        int4 v = src[off];
        dst[off] = (v.x & 0xFF) | ((v.y & 0xFF) << 8) | ((v.z & 0xFF) << 16) | (v.w << 24);
    }
}
__global__ void __launch_bounds__(256) k_pack_one(
    const int4* __restrict__ src, uint32_t* __restrict__ dst, int n4)
{
    int i = (blockIdx.x * 256 + threadIdx.x) * 2;
    #pragma unroll
    for (int r = 0; r < 2; r++, i++) {
        if (i >= n4) break;
        int4 v = src[i];
        dst[i] = (v.x & 0xFF) | ((v.y & 0xFF) << 8) | ((v.z & 0xFF) << 16) | (v.w << 24);
    }
}

// ---------------- device helpers ----------------
__device__ __forceinline__ uint32_t smem_u32(const void* p) {
    uint32_t a;
    asm("{ .reg .u64 t; cvta.to.shared.u64 t, %1; cvt.u32.u64 %0, t; }" : "=r"(a) : "l"(p));
    return a;
}
__device__ __forceinline__ void mbar_init(uint32_t a, uint32_t cnt) {
    asm volatile("mbarrier.init.shared.b64 [%0], %1;" :: "r"(a), "r"(cnt) : "memory");
}
__device__ __forceinline__ void fence_async() {
    asm volatile("fence.proxy.async.shared::cta;" ::: "memory");
}
__device__ __forceinline__ void mbar_expect_tx(uint32_t a, uint32_t bytes) {
    asm volatile("mbarrier.arrive.expect_tx.shared.b64 _, [%0], %1;" :: "r"(a), "r"(bytes) : "memory");
}
__device__ __forceinline__ void mbar_arrive(uint32_t a) {
    asm volatile("mbarrier.arrive.shared.b64 _, [%0];" :: "r"(a) : "memory");
}
__device__ __forceinline__ void mbar_wait(uint32_t a, uint32_t parity) {
    asm volatile(
        "{\n\t.reg .pred P;\n\t"
        "W_%=:\n\t"
        "mbarrier.try_wait.parity.acquire.cta.shared::cta.b64 P, [%0], %1, 0x989680;\n\t"
        "@P bra.uni D_%=;\n\t"
        "bra.uni W_%=;\n\t"
        "D_%=:\n\t}"
        :: "r"(a), "r"(parity) : "memory");
}
__device__ __forceinline__ void tma2d(uint32_t dst, const void* tmap, int cx, int cy, uint32_t bar) {
    asm volatile(
        "cp.async.bulk.tensor.2d.shared::cta.global.tile.mbarrier::complete_tx::bytes "
        "[%0], [%1, {%2, %3}], [%4];"
        :: "r"(dst), "l"(tmap), "r"(cx), "r"(cy), "r"(bar) : "memory");
}
__device__ __forceinline__ void ldsm4(uint32_t* r, uint32_t addr) {
    asm volatile("ldmatrix.sync.aligned.m8n8.x4.shared.b16 {%0,%1,%2,%3}, [%4];"
                 : "=r"(r[0]), "=r"(r[1]), "=r"(r[2]), "=r"(r[3]) : "r"(addr));
}
__device__ __forceinline__ void mma_s8(int* c, const uint32_t* a, const uint32_t* b) {
    asm volatile(
        "mma.sync.aligned.m16n8k32.row.col.s32.s8.s8.s32 "
        "{%0,%1,%2,%3}, {%4,%5,%6,%7}, {%8,%9}, {%0,%1,%2,%3};"
        : "+r"(c[0]), "+r"(c[1]), "+r"(c[2]), "+r"(c[3])
        : "r"(a[0]), "r"(a[1]), "r"(a[2]), "r"(a[3]), "r"(b[0]), "r"(b[1]));
}

// ---------------- generic 128x128 W8A8 GEMM mainloop (NS=3, 2 CTA/SM) ----------------
#define STG 32768
#define NS3 3
#define SMEMP (NS3 * STG + 1024)    // 99328

#define GEMM_MAINLOOP(tmA_, tmB_, m0_, n0_, KIT_)                                        \
    if (tid == 0) {                                                                      \
        for (int s = 0; s < NS3; s++) {                                                  \
            mbar_init(smem_u32(&bfull[s]), 1);                                           \
            mbar_init(smem_u32(&bempty[s]), 8);                                          \
        }                                                                                \
        fence_async();                                                                   \
    }                                                                                    \
    __syncthreads();                                                                     \
    auto issue = [&](int k) {                                                            \
        int s = k % NS3;                                                                 \
        uint32_t bar = smem_u32(&bfull[s]);                                              \
        mbar_expect_tx(bar, STG);                                                        \
        uint32_t dst = base + s * STG;                                                   \
        tma2d(dst,         &tmA_, k * 128, m0_, bar);                                    \
        tma2d(dst + 16384, &tmB_, k * 128, n0_, bar);                                    \
    };                                                                                   \
    if (tid == 0) { issue(0); issue(1); }                                                \
    const int t8 = lane >> 3;                                                            \
    const int r8 = lane & 7;                                                             \
    for (int k = 0; k < KIT_; k++) {                                                     \
        int ks_ = k % NS3;                                                               \
        if (tid == 0 && k + 2 < KIT_) {                                                  \
            if (k >= 1) mbar_wait(smem_u32(&bempty[(k - 1) % NS3]), ((k - 1) / NS3) & 1);\
            issue(k + 2);                                                                \
        }                                                                                \
        mbar_wait(smem_u32(&bfull[ks_]), (k / NS3) & 1);                                 \
        uint32_t sA = base + ks_ * STG;                                                  \
        uint32_t sB = sA + 16384;                                                        \
        _Pragma("unroll")                                                                \
        for (int kq = 0; kq < 4; kq++) {                                                 \
            const int kb = kq * 32;                                                      \
            uint32_t a[4][4];                                                            \
            _Pragma("unroll")                                                            \
            for (int mf = 0; mf < 4; mf++) {                                             \
                int row = wm * 64 + mf * 16 + (t8 & 1) * 8 + r8;                         \
                int kby = kb + (t8 >> 1) * 16;                                           \
                ldsm4(a[mf], sA + row * 128 + (kby ^ ((row & 7) << 4)));                 \
            }                                                                            \
            uint32_t b2[2][4];                                                           \
            _Pragma("unroll")                                                            \
            for (int p = 0; p < 2; p++) {                                                \
                int nrow = wn * 32 + p * 16 + (t8 >> 1) * 8 + r8;                        \
                int kby = kb + (t8 & 1) * 16;                                            \
                ldsm4(b2[p], sB + nrow * 128 + (kby ^ ((nrow & 7) << 4)));               \
            }                                                                            \
            _Pragma("unroll")                                                            \
            for (int mf = 0; mf < 4; mf++)                                               \
                _Pragma("unroll")                                                        \
                for (int nf = 0; nf < 4; nf++)                                           \
                    mma_s8(c[mf][nf], a[mf], &b2[nf >> 1][(nf & 1) * 2]);                \
        }                                                                                \
        if (lane == 0) mbar_arrive(smem_u32(&bempty[ks_]));                              \
    }

// ---------------- gate proj: quant(relu) -> g8 ----------------
__global__ void __launch_bounds__(256, 2) k_gate(
    const __grid_constant__ CUtensorMap tmX,
    const __grid_constant__ CUtensorMap tmW,
    const int* __restrict__ biasv,
    const float* __restrict__ salpha, const float* __restrict__ sbeta)
{
    extern __shared__ char smem[];
    __shared__ __align__(8) uint64_t bfull[NS3], bempty[NS3];
    const uint32_t raw = smem_u32(smem);
    const uint32_t base = (raw + 1023u) & ~1023u;
    char* smA = smem + (base - raw);
    const int tid = threadIdx.x;
    const int lane = tid & 31;
    const int wid = tid >> 5;
    const int wm = wid >> 2, wn = wid & 3;
    const int m0 = (blockIdx.x & 31) << 7;
    const int f0 = (blockIdx.x >> 5) << 7;

    int c[4][4][4];
    #pragma unroll
    for (int i = 0; i < 4; i++)
        #pragma unroll
        for (int j = 0; j < 4; j++)
            #pragma unroll
            for (int t = 0; t < 4; t++) c[i][j][t] = 0;

    GEMM_MAINLOOP(tmX, tmW, m0, f0, (H_DIM / 128))

    __syncthreads();
    const float alpha = *salpha, beta = *sbeta;
    float bb[4][2];
    #pragma unroll
    for (int nf = 0; nf < 4; nf++) {
        int f = f0 + wn * 32 + nf * 8 + 2 * (lane & 3);
        bb[nf][0] = __fmul_rn(beta, (float)biasv[f]);
        bb[nf][1] = __fmul_rn(beta, (float)biasv[f + 1]);
    }
    unsigned short* sp = (unsigned short*)smA;
    #pragma unroll
    for (int mf = 0; mf < 4; mf++)
        #pragma unroll
        for (int nf = 0; nf < 4; nf++) {
            int col = wn * 32 + nf * 8 + 2 * (lane & 3);
            int r0 = wm * 64 + mf * 16 + (lane >> 2);
            #pragma unroll
            for (int h = 0; h < 2; h++) {
                int row = r0 + h * 8;
                float v0 = __fadd_rn(__fmul_rn(alpha, (float)c[mf][nf][h * 2 + 0]), bb[nf][0]);
                float v1 = __fadd_rn(__fmul_rn(alpha, (float)c[mf][nf][h * 2 + 1]), bb[nf][1]);
                int i0 = min(__float2int_rn(fmaxf(v0, 0.0f)), 127);
                int i1 = min(__float2int_rn(fmaxf(v1, 0.0f)), 127);
                sp[(row * 128 + col) >> 1] = (unsigned short)((uint32_t)i0 | ((uint32_t)i1 << 8));
            }
        }
    __syncthreads();
    const int4* s4 = (const int4*)smA;
    #pragma unroll
    for (int i = 0; i < 4; i++) {
        int lin = i * 256 + tid;
        int row = lin >> 3, ch = lin & 7;
        *(int4*)(g_g8 + (size_t)(m0 + row) * F_DIM + f0 + ch * 16) = s4[lin];
    }
}

// ---------------- up proj: quant -> u8, product with g8 -> prod8 ----------------
__global__ void __launch_bounds__(256, 2) k_up_prod(
    const __grid_constant__ CUtensorMap tmX,
    const __grid_constant__ CUtensorMap tmW,
    const int* __restrict__ biasv,
    const float* __restrict__ salpha, const float* __restrict__ sbeta)
{
    extern __shared__ char smem[];
    __shared__ __align__(8) uint64_t bfull[NS3], bempty[NS3];
    const uint32_t raw = smem_u32(smem);
    const uint32_t base = (raw + 1023u) & ~1023u;
    char* smA = smem + (base - raw);
    const int tid = threadIdx.x;
    const int lane = tid & 31;
    const int wid = tid >> 5;
    const int wm = wid >> 2, wn = wid & 3;
    const int m0 = (blockIdx.x & 31) << 7;
    const int f0 = (blockIdx.x >> 5) << 7;

    int c[4][4][4];
    #pragma unroll
    for (int i = 0; i < 4; i++)
        #pragma unroll
        for (int j = 0; j < 4; j++)
            #pragma unroll
            for (int t = 0; t < 4; t++) c[i][j][t] = 0;

    GEMM_MAINLOOP(tmX, tmW, m0, f0, (H_DIM / 128))

    __syncthreads();
    const float alpha = *salpha, beta = *sbeta;
    float bb[4][2];
    #pragma unroll
    for (int nf = 0; nf < 4; nf++) {
        int f = f0 + wn * 32 + nf * 8 + 2 * (lane & 3);
        bb[nf][0] = __fmul_rn(beta, (float)biasv[f]);
        bb[nf][1] = __fmul_rn(beta, (float)biasv[f + 1]);
    }
    unsigned short* sp = (unsigned short*)smA;
    #pragma unroll
    for (int mf = 0; mf < 4; mf++)
        #pragma unroll
        for (int nf = 0; nf < 4; nf++) {
            int col = wn * 32 + nf * 8 + 2 * (lane & 3);
            int r0 = wm * 64 + mf * 16 + (lane >> 2);
            #pragma unroll
            for (int h = 0; h < 2; h++) {
                int row = r0 + h * 8;
                float v0 = __fadd_rn(__fmul_rn(alpha, (float)c[mf][nf][h * 2 + 0]), bb[nf][0]);
                float v1 = __fadd_rn(__fmul_rn(alpha, (float)c[mf][nf][h * 2 + 1]), bb[nf][1]);
                int i0 = max(-128, min(127, __float2int_rn(v0)));
                int i1 = max(-128, min(127, __float2int_rn(v1)));
                sp[(row * 128 + col) >> 1] =
                    (unsigned short)((uint32_t)(i0 & 0xFF) | ((uint32_t)(i1 & 0xFF) << 8));
            }
        }
    __syncthreads();
    const uint4* s4 = (const uint4*)smA;
    #pragma unroll
    for (int i = 0; i < 4; i++) {
        int lin = i * 256 + tid;
        int row = lin >> 3, ch = lin & 7;
        const size_t off = (size_t)(m0 + row) * F_DIM + f0 + ch * 16;
        uint4 u = s4[lin];
        uint4 g = *(const uint4*)(g_g8 + off);
        uint4 r;
        uint32_t* up = (uint32_t*)&u;
        uint32_t* gp = (uint32_t*)&g;
        uint32_t* rp = (uint32_t*)&r;
        #pragma unroll
        for (int q = 0; q < 4; q++) {
            uint32_t res = 0;
            #pragma unroll
            for (int b = 0; b < 4; b++) {
                int gv = (gp[q] >> (8 * b)) & 0xFF;
                int uv = (int)(int8_t)((up[q] >> (8 * b)) & 0xFF);
                res |= (uint32_t)((gv * uv) & 0xFF) << (8 * b);
            }
            rp[q] = res;
        }
        *(uint4*)(g_prod8 + off) = r;
    }
}

// ---------------- down proj: fp32 dequant + bias ----------------
__global__ void __launch_bounds__(256, 2) k_down(
    const __grid_constant__ CUtensorMap tmA,
    const __grid_constant__ CUtensorMap tmW,
    const float* __restrict__ sad, const float* __restrict__ bias,
    float* __restrict__ out)
{
    extern __shared__ char smem[];
    __shared__ __align__(8) uint64_t bfull[NS3], bempty[NS3];
    const uint32_t raw = smem_u32(smem);
    const uint32_t base = (raw + 1023u) & ~1023u;
    char* smA = smem + (base - raw);
    const int tid = threadIdx.x;
    const int lane = tid & 31;
    const int wid = tid >> 5;
    const int wm = wid >> 2, wn = wid & 3;
    const int m0 = (blockIdx.x & 31) << 7;
    const int n0 = (blockIdx.x >> 5) << 7;

    int c[4][4][4];
    #pragma unroll
    for (int i = 0; i < 4; i++)
        #pragma unroll
        for (int j = 0; j < 4; j++)
            #pragma unroll
            for (int t = 0; t < 4; t++) c[i][j][t] = 0;

    GEMM_MAINLOOP(tmA, tmW, m0, n0, (F_DIM / 128))

    __syncthreads();
    const float ad = *sad;
    float bb[4][2];
    #pragma unroll
    for (int nf = 0; nf < 4; nf++) {
        int h = n0 + wn * 32 + nf * 8 + 2 * (lane & 3);
        bb[nf][0] = bias[h];
        bb[nf][1] = bias[h + 1];
    }
    float* sf = (float*)smA;
    #pragma unroll
    for (int mf = 0; mf < 4; mf++)
        #pragma unroll
        for (int nf = 0; nf < 4; nf++) {
            int col = wn * 32 + nf * 8 + 2 * (lane & 3);
            int r0 = wm * 64 + mf * 16 + (lane >> 2);
            #pragma unroll
            for (int h = 0; h < 2; h++) {
                int row = r0 + h * 8;
                float2 v;
                v.x = __fadd_rn(__fmul_rn(ad, (float)c[mf][nf][h * 2 + 0]), bb[nf][0]);
                v.y = __fadd_rn(__fmul_rn(ad, (float)c[mf][nf][h * 2 + 1]), bb[nf][1]);
                *(float2*)(sf + row * 128 + col) = v;
            }
        }
    __syncthreads();
    const float4* s4 = (const float4*)smA;
    #pragma unroll
    for (int i = 0; i < 16; i++) {
        int lin = i * 256 + tid;
        int row = lin >> 5, ch = lin & 31;
        *(float4*)(out + (size_t)(m0 + row) * H_DIM + n0 + ch * 4) = s4[lin];
    }
}

// ---------------- host ----------------
typedef CUresult (*EncodeFn)(CUtensorMap*, CUtensorMapDataType, cuuint32_t, void*,
                             const cuuint64_t*, const cuuint64_t*, const cuuint32_t*,
                             const cuuint32_t*, CUtensorMapInterleave, CUtensorMapSwizzle,
                             CUtensorMapL2promotion, CUtensorMapFloatOOBfill);

static EncodeFn get_encoder() {
    static EncodeFn fn = nullptr;
    if (!fn) {
        cudaDriverEntryPointQueryResult st;
        void* p = nullptr;
        cudaGetDriverEntryPoint("cuTensorMapEncodeTiled", &p, cudaEnableDefault, &st);
        fn = (EncodeFn)p;
    }
    return fn;
}

static void make_tm_i8(CUtensorMap* tm, void* ptr, uint64_t d0, uint64_t d1) {
    cuuint64_t dims[2] = {d0, d1};
    cuuint64_t strides[1] = {d0};
    cuuint32_t box[2] = {128, 128};
    cuuint32_t es[2] = {1, 1};
    get_encoder()(tm, CU_TENSOR_MAP_DATA_TYPE_UINT8, 2, ptr, dims, strides, box, es,
                  CU_TENSOR_MAP_INTERLEAVE_NONE, CU_TENSOR_MAP_SWIZZLE_128B,
                  CU_TENSOR_MAP_L2_PROMOTION_L2_128B, CU_TENSOR_MAP_FLOAT_OOB_FILL_NONE);
}

extern "C" void kernel_launch(void* const* d_in, const int* in_sizes, int n_in,
                              void* d_out, int out_size) {
    (void)out_size;
    int idxX = -1, idxBias = -1;
    int idxW[4]; int nW = 0;
    int idxB[4]; int nB = 0;
    int idxS[8]; int nS = 0;
    for (int i = 0; i < n_in; i++) {
        long long s = in_sizes[i];
        if (s == (long long)M_TOK * H_DIM)      idxX = i;
        else if (s == (long long)F_DIM * H_DIM) { if (nW < 4) idxW[nW++] = i; }
        else if (s == F_DIM)                    { if (nB < 4) idxB[nB++] = i; }
        else if (s == H_DIM)                    idxBias = i;
        else if (s == 1)                        { if (nS < 8) idxS[nS++] = i; }
    }
    const bool dict_like = (idxX >= 0 && nW == 3 && idxX < idxW[0]);

    const int4* X32  = (const int4*)d_in[idxX];
    const int4* Wg32 = (const int4*)d_in[dict_like ? idxW[0] : idxW[1]];
    const int4* Wu32 = (const int4*)d_in[dict_like ? idxW[1] : idxW[2]];
    const int4* Wd32 = (const int4*)d_in[dict_like ? idxW[2] : idxW[0]];
    const int* bg = (const int*)d_in[idxB[0]];
    const int* bu = (const int*)d_in[idxB[1]];
    const float* b_d = (const float*)d_in[idxBias];
    const float *a_g, *b_g, *a_u, *b_u, *a_d;
    if (dict_like) {
        a_g = (const float*)d_in[idxS[0]];
        b_g = (const float*)d_in[idxS[1]];
        a_u = (const float*)d_in[idxS[2]];
        b_u = (const float*)d_in[idxS[3]];
        a_d = (const float*)d_in[idxS[4]];
    } else {
        a_d = (const float*)d_in[idxS[0]];
        a_g = (const float*)d_in[idxS[1]];
        a_u = (const float*)d_in[idxS[2]];
        b_g = (const float*)d_in[idxS[3]];
        b_u = (const float*)d_in[idxS[4]];
    }
    float* out = (float*)d_out;

    void *x8, *wg8, *wu8, *wd8, *prod;
    cudaGetSymbolAddress(&x8,  g_x8);
    cudaGetSymbolAddress(&wg8, g_wg8);
    cudaGetSymbolAddress(&wu8, g_wu8);
    cudaGetSymbolAddress(&wd8, g_wd8);
    cudaGetSymbolAddress(&prod, g_prod8);

    CUtensorMap tmX, tmG, tmU, tmA, tmW;
    make_tm_i8(&tmX, x8,   H_DIM, M_TOK);
    make_tm_i8(&tmG, wg8,  H_DIM, F_DIM);
    make_tm_i8(&tmU, wu8,  H_DIM, F_DIM);
    make_tm_i8(&tmA, prod, F_DIM, M_TOK);
    make_tm_i8(&tmW, wd8,  F_DIM, H_DIM);

    cudaFuncSetAttribute(k_gate,    cudaFuncAttributeMaxDynamicSharedMemorySize, SMEMP);
    cudaFuncSetAttribute(k_up_prod, cudaFuncAttributeMaxDynamicSharedMemorySize, SMEMP);
    cudaFuncSetAttribute(k_down,    cudaFuncAttributeMaxDynamicSharedMemorySize, SMEMP);

    // ---- side streams + events for forked pack (created once; graph-capture safe) ----
    static cudaStream_t s1 = nullptr, s2 = nullptr;
    static cudaEvent_t eFork = nullptr, eWu = nullptr, eWd = nullptr;
    if (!s1) {
        cudaStreamCreateWithFlags(&s1, cudaStreamNonBlocking);
        cudaStreamCreateWithFlags(&s2, cudaStreamNonBlocking);
        cudaEventCreateWithFlags(&eFork, cudaEventDisableTiming);
        cudaEventCreateWithFlags(&eWu,   cudaEventDisableTiming);
        cudaEventCreateWithFlags(&eWd,   cudaEventDisableTiming);
    }

    const int n4x = (M_TOK * H_DIM) / 4;
    const int n4w = (F_DIM * H_DIM) / 4;

    // fork
    cudaEventRecord(eFork, 0);
    cudaStreamWaitEvent(s1, eFork, 0);
    cudaStreamWaitEvent(s2, eFork, 0);
    // side packs overlap the gate GEMM (DRAM-idle)
    k_pack_one<<<(n4w / 2 + 255) / 256, 256, 0, s1>>>(Wu32, (uint32_t*)wu8, n4w);
    cudaEventRecord(eWu, s1);
    k_pack_one<<<(n4w / 2 + 255) / 256, 256, 0, s2>>>(Wd32, (uint32_t*)wd8, n4w);
    cudaEventRecord(eWd, s2);
    // main path: pack X+Wg, then gate
    k_pack_xg<<<((n4x + n4w) / 2 + 255) / 256, 256>>>(X32, Wg32, (uint32_t*)x8, (uint32_t*)wg8, n4x, n4w);

    const int grid1 = (M_TOK / 128) * (F_DIM / 128);   // 2752
    const int grid2 = (M_TOK / 128) * (H_DIM / 128);   // 1024
    k_gate<<<grid1, 256, SMEMP>>>(tmX, tmG, bg, a_g, b_g);
    cudaStreamWaitEvent(0, eWu, 0);                    // join Wu pack
    k_up_prod<<<grid1, 256, SMEMP>>>(tmX, tmU, bu, a_u, b_u);
    cudaStreamWaitEvent(0, eWd, 0);                    // join Wd pack
    k_down<<<grid2, 256, SMEMP>>>(tmA, tmW, a_d, b_d, out);
}

// round 16
// speedup vs baseline: 1.0053x; 1.0053x over previous
#include <cuda_runtime.h>
#include <cuda.h>
#include <cstdint>

#define M_TOK 4096
#define H_DIM 4096
#define F_DIM 11008

static __device__ __align__(1024) int8_t g_x8[(size_t)M_TOK * H_DIM];
static __device__ __align__(1024) int8_t g_wg8[(size_t)F_DIM * H_DIM];
static __device__ __align__(1024) int8_t g_wu8[(size_t)F_DIM * H_DIM];
static __device__ __align__(1024) int8_t g_wd8[(size_t)H_DIM * F_DIM];
static __device__ __align__(1024) int8_t g_g8[(size_t)M_TOK * F_DIM];
static __device__ __align__(1024) int8_t g_prod8[(size_t)M_TOK * F_DIM];

// cross-phase sync state (zeroed per launch via cudaMemsetAsync)
struct SyncState {
    int gate_flag[2752];   // gate tile t done (g8 visible)
    int row_cnt[32];       // # up tiles done per m-row-block (target 86)
    int wu_cnt, wd_cnt;    // pack completion counters
    int wu_ready, wd_ready;
};
static __device__ SyncState g_sync;

// ---------------- pack kernels ----------------
__global__ void __launch_bounds__(256) k_pack_xg(
    const int4* __restrict__ sX, const int4* __restrict__ sG,
    uint32_t* __restrict__ dX, uint32_t* __restrict__ dG, int n4x, int n4w)
{
    int i = (blockIdx.x * 256 + threadIdx.x) * 2;
    #pragma unroll
    for (int r = 0; r < 2; r++, i++) {
        const int4* src; uint32_t* dst; int off;
        if (i < n4x)            { src = sX; dst = dX; off = i; }
        else if (i < n4x + n4w) { src = sG; dst = dG; off = i - n4x; }
        else break;
        int4 v = src[off];
        dst[off] = (v.x & 0xFF) | ((v.y & 0xFF) << 8) | ((v.z & 0xFF) << 16) | (v.w << 24);
    }
}
// throttled grid-stride side pack; publishes ready flag when all blocks done
__global__ void __launch_bounds__(256) k_pack_side(
    const int4* __restrict__ src, uint32_t* __restrict__ dst, int n4, int sel)
{
    for (int i = blockIdx.x * 256 + threadIdx.x; i < n4; i += gridDim.x * 256) {
        int4 v = src[i];
        dst[i] = (v.x & 0xFF) | ((v.y & 0xFF) << 8) | ((v.z & 0xFF) << 16) | (v.w << 24);
    }
    __threadfence();
    __syncthreads();
    if (threadIdx.x == 0) {
        int* cnt   = sel ? &g_sync.wd_cnt   : &g_sync.wu_cnt;
        int* ready = sel ? &g_sync.wd_ready : &g_sync.wu_ready;
        int old = atomicAdd(cnt, 1);
        if (old == (int)gridDim.x - 1) atomicExch(ready, 1);
    }
}

// ---------------- device helpers ----------------
__device__ __forceinline__ uint32_t smem_u32(const void* p) {
    uint32_t a;
    asm("{ .reg .u64 t; cvta.to.shared.u64 t, %1; cvt.u32.u64 %0, t; }" : "=r"(a) : "l"(p));
    return a;
}
__device__ __forceinline__ void mbar_init(uint32_t a, uint32_t cnt) {
    asm volatile("mbarrier.init.shared.b64 [%0], %1;" :: "r"(a), "r"(cnt) : "memory");
}
__device__ __forceinline__ void fence_async() {
    asm volatile("fence.proxy.async.shared::cta;" ::: "memory");
}
__device__ __forceinline__ void mbar_expect_tx(uint32_t a, uint32_t bytes) {
    asm volatile("mbarrier.arrive.expect_tx.shared.b64 _, [%0], %1;" :: "r"(a), "r"(bytes) : "memory");
}
__device__ __forceinline__ void mbar_arrive(uint32_t a) {
    asm volatile("mbarrier.arrive.shared.b64 _, [%0];" :: "r"(a) : "memory");
}
__device__ __forceinline__ void mbar_wait(uint32_t a, uint32_t parity) {
    asm volatile(
        "{\n\t.reg .pred P;\n\t"
        "W_%=:\n\t"
        "mbarrier.try_wait.parity.acquire.cta.shared::cta.b64 P, [%0], %1, 0x989680;\n\t"
        "@P bra.uni D_%=;\n\t"
        "bra.uni W_%=;\n\t"
        "D_%=:\n\t}"
        :: "r"(a), "r"(parity) : "memory");
}
__device__ __forceinline__ void tma2d(uint32_t dst, const void* tmap, int cx, int cy, uint32_t bar) {
    asm volatile(
        "cp.async.bulk.tensor.2d.shared::cta.global.tile.mbarrier::complete_tx::bytes "
        "[%0], [%1, {%2, %3}], [%4];"
        :: "r"(dst), "l"(tmap), "r"(cx), "r"(cy), "r"(bar) : "memory");
}
__device__ __forceinline__ void ldsm4(uint32_t* r, uint32_t addr) {
    asm volatile("ldmatrix.sync.aligned.m8n8.x4.shared.b16 {%0,%1,%2,%3}, [%4];"
                 : "=r"(r[0]), "=r"(r[1]), "=r"(r[2]), "=r"(r[3]) : "r"(addr));
}
__device__ __forceinline__ void mma_s8(int* c, const uint32_t* a, const uint32_t* b) {
    asm volatile(
        "mma.sync.aligned.m16n8k32.row.col.s32.s8.s8.s32 "
        "{%0,%1,%2,%3}, {%4,%5,%6,%7}, {%8,%9}, {%0,%1,%2,%3};"
        : "+r"(c[0]), "+r"(c[1]), "+r"(c[2]), "+r"(c[3])
        : "r"(a[0]), "r"(a[1]), "r"(a[2]), "r"(a[3]), "r"(b[0]), "r"(b[1]));
}
__device__ __forceinline__ int ld_acq(const int* p) {
    int v;
    asm volatile("ld.acquire.gpu.b32 %0, [%1];" : "=r"(v) : "l"(p) : "memory");
    return v;
}
__device__ __forceinline__ void wait_flag(const int* p, int target) {
    if (threadIdx.x == 0) {
        while (ld_acq(p) < target) __nanosleep(200);
    }
    __syncthreads();
}

// ---------------- generic 128x128 W8A8 GEMM mainloop (NS=3, 2 CTA/SM) ----------------
#define STG 32768
#define NS3 3
#define SMEMP (NS3 * STG + 1024)    // 99328

#define GEMM_MAINLOOP(tmA_, tmB_, m0_, n0_, KIT_)                                        \
    if (tid == 0) {                                                                      \
        for (int s = 0; s < NS3; s++) {                                                  \
            mbar_init(smem_u32(&bfull[s]), 1);                                           \
            mbar_init(smem_u32(&bempty[s]), 8);                                          \
        }                                                                                \
        fence_async();                                                                   \
    }                                                                                    \
    __syncthreads();                                                                     \
    auto issue = [&](int k) {                                                            \
        int s = k % NS3;                                                                 \
        uint32_t bar = smem_u32(&bfull[s]);                                              \
        mbar_expect_tx(bar, STG);                                                        \
        uint32_t dst = base + s * STG;                                                   \
        tma2d(dst,         &tmA_, k * 128, m0_, bar);                                    \
        tma2d(dst + 16384, &tmB_, k * 128, n0_, bar);                                    \
    };                                                                                   \
    if (tid == 0) { issue(0); issue(1); }                                                \
    const int t8 = lane >> 3;                                                            \
    const int r8 = lane & 7;                                                             \
    for (int k = 0; k < KIT_; k++) {                                                     \
        int ks_ = k % NS3;                                                               \
        if (tid == 0 && k + 2 < KIT_) {                                                  \
            if (k >= 1) mbar_wait(smem_u32(&bempty[(k - 1) % NS3]), ((k - 1) / NS3) & 1);\
            issue(k + 2);                                                                \
        }                                                                                \
        mbar_wait(smem_u32(&bfull[ks_]), (k / NS3) & 1);                                 \
        uint32_t sA = base + ks_ * STG;                                                  \
        uint32_t sB = sA + 16384;                                                        \
        _Pragma("unroll")                                                                \
        for (int kq = 0; kq < 4; kq++) {                                                 \
            const int kb = kq * 32;                                                      \
            uint32_t a[4][4];                                                            \
            _Pragma("unroll")                                                            \
            for (int mf = 0; mf < 4; mf++) {                                             \
                int row = wm * 64 + mf * 16 + (t8 & 1) * 8 + r8;                         \
                int kby = kb + (t8 >> 1) * 16;                                           \
                ldsm4(a[mf], sA + row * 128 + (kby ^ ((row & 7) << 4)));                 \
            }                                                                            \
            uint32_t b2[2][4];                                                           \
            _Pragma("unroll")                                                            \
            for (int p = 0; p < 2; p++) {                                                \
                int nrow = wn * 32 + p * 16 + (t8 >> 1) * 8 + r8;                        \
                int kby = kb + (t8 & 1) * 16;                                            \
                ldsm4(b2[p], sB + nrow * 128 + (kby ^ ((nrow & 7) << 4)));               \
            }                                                                            \
            _Pragma("unroll")                                                            \
            for (int mf = 0; mf < 4; mf++)                                               \
                _Pragma("unroll")                                                        \
                for (int nf = 0; nf < 4; nf++)                                           \
                    mma_s8(c[mf][nf], a[mf], &b2[nf >> 1][(nf & 1) * 2]);                \
        }                                                                                \
        if (lane == 0) mbar_arrive(smem_u32(&bempty[ks_]));                              \
    }

#define N_GATE 2752
#define N_UP   2752
#define N_DOWN 1024

// ---------------- mega kernel: gate -> up(+product) -> down, one launch ----------------
__global__ void __launch_bounds__(256, 2) k_mega(
    const __grid_constant__ CUtensorMap tmX,
    const __grid_constant__ CUtensorMap tmG,
    const __grid_constant__ CUtensorMap tmU,
    const __grid_constant__ CUtensorMap tmA,
    const __grid_constant__ CUtensorMap tmW,
    const int* __restrict__ bgv, const int* __restrict__ buv,
    const float* __restrict__ sag, const float* __restrict__ sbg,
    const float* __restrict__ sau, const float* __restrict__ sbu,
    const float* __restrict__ sad, const float* __restrict__ bias,
    float* __restrict__ out)
{
    extern __shared__ char smem[];
    __shared__ __align__(8) uint64_t bfull[NS3], bempty[NS3];
    const uint32_t raw = smem_u32(smem);
    const uint32_t base = (raw + 1023u) & ~1023u;
    char* smA = smem + (base - raw);
    const int tid = threadIdx.x;
    const int lane = tid & 31;
    const int wid = tid >> 5;
    const int wm = wid >> 2, wn = wid & 3;
    const int bid = blockIdx.x;

    if (bid < N_GATE) {
        // ======== gate phase (f-fastest tile order) ========
        const int t = bid;
        const int m0 = (t / 86) << 7;
        const int f0 = (t % 86) << 7;

        int c[4][4][4];
        #pragma unroll
        for (int i = 0; i < 4; i++)
            #pragma unroll
            for (int j = 0; j < 4; j++)
                #pragma unroll
                for (int q = 0; q < 4; q++) c[i][j][q] = 0;

        GEMM_MAINLOOP(tmX, tmG, m0, f0, (H_DIM / 128))

        __syncthreads();
        const float alpha = *sag, beta = *sbg;
        float bb[4][2];
        #pragma unroll
        for (int nf = 0; nf < 4; nf++) {
            int f = f0 + wn * 32 + nf * 8 + 2 * (lane & 3);
            bb[nf][0] = __fmul_rn(beta, (float)bgv[f]);
            bb[nf][1] = __fmul_rn(beta, (float)bgv[f + 1]);
        }
        unsigned short* sp = (unsigned short*)smA;
        #pragma unroll
        for (int mf = 0; mf < 4; mf++)
            #pragma unroll
            for (int nf = 0; nf < 4; nf++) {
                int col = wn * 32 + nf * 8 + 2 * (lane & 3);
                int r0 = wm * 64 + mf * 16 + (lane >> 2);
                #pragma unroll
                for (int h = 0; h < 2; h++) {
                    int row = r0 + h * 8;
                    float v0 = __fadd_rn(__fmul_rn(alpha, (float)c[mf][nf][h * 2 + 0]), bb[nf][0]);
                    float v1 = __fadd_rn(__fmul_rn(alpha, (float)c[mf][nf][h * 2 + 1]), bb[nf][1]);
                    int i0 = min(__float2int_rn(fmaxf(v0, 0.0f)), 127);
                    int i1 = min(__float2int_rn(fmaxf(v1, 0.0f)), 127);
                    sp[(row * 128 + col) >> 1] = (unsigned short)((uint32_t)i0 | ((uint32_t)i1 << 8));
                }
            }
        __syncthreads();
        const int4* s4 = (const int4*)smA;
        #pragma unroll
        for (int i = 0; i < 4; i++) {
            int lin = i * 256 + tid;
            int row = lin >> 3, ch = lin & 7;
            *(int4*)(g_g8 + (size_t)(m0 + row) * F_DIM + f0 + ch * 16) = s4[lin];
        }
        // publish tile
        __threadfence();
        __syncthreads();
        if (tid == 0) atomicExch(&g_sync.gate_flag[t], 1);

    } else if (bid < N_GATE + N_UP) {
        // ======== up phase (+ product) ========
        const int t = bid - N_GATE;
        const int m0 = (t / 86) << 7;
        const int f0 = (t % 86) << 7;

        wait_flag(&g_sync.wu_ready, 1);   // wu8 packed

        int c[4][4][4];
        #pragma unroll
        for (int i = 0; i < 4; i++)
            #pragma unroll
            for (int j = 0; j < 4; j++)
                #pragma unroll
                for (int q = 0; q < 4; q++) c[i][j][q] = 0;

        GEMM_MAINLOOP(tmX, tmU, m0, f0, (H_DIM / 128))

        __syncthreads();
        const float alpha = *sau, beta = *sbu;
        float bb[4][2];
        #pragma unroll
        for (int nf = 0; nf < 4; nf++) {
            int f = f0 + wn * 32 + nf * 8 + 2 * (lane & 3);
            bb[nf][0] = __fmul_rn(beta, (float)buv[f]);
            bb[nf][1] = __fmul_rn(beta, (float)buv[f + 1]);
        }
        unsigned short* sp = (unsigned short*)smA;
        #pragma unroll
        for (int mf = 0; mf < 4; mf++)
            #pragma unroll
            for (int nf = 0; nf < 4; nf++) {
                int col = wn * 32 + nf * 8 + 2 * (lane & 3);
                int r0 = wm * 64 + mf * 16 + (lane >> 2);
                #pragma unroll
                for (int h = 0; h < 2; h++) {
                    int row = r0 + h * 8;
                    float v0 = __fadd_rn(__fmul_rn(alpha, (float)c[mf][nf][h * 2 + 0]), bb[nf][0]);
                    float v1 = __fadd_rn(__fmul_rn(alpha, (float)c[mf][nf][h * 2 + 1]), bb[nf][1]);
                    int i0 = max(-128, min(127, __float2int_rn(v0)));
                    int i1 = max(-128, min(127, __float2int_rn(v1)));
                    sp[(row * 128 + col) >> 1] =
                        (unsigned short)((uint32_t)(i0 & 0xFF) | ((uint32_t)(i1 & 0xFF) << 8));
                }
            }
        __syncthreads();
        wait_flag(&g_sync.gate_flag[t], 1);   // g8 tile visible
        const uint4* s4 = (const uint4*)smA;
        #pragma unroll
        for (int i = 0; i < 4; i++) {
            int lin = i * 256 + tid;
            int row = lin >> 3, ch = lin & 7;
            const size_t off = (size_t)(m0 + row) * F_DIM + f0 + ch * 16;
            uint4 u = s4[lin];
            uint4 g = *(const uint4*)(g_g8 + off);
            uint4 r;
            uint32_t* up = (uint32_t*)&u;
            uint32_t* gp = (uint32_t*)&g;
            uint32_t* rp = (uint32_t*)&r;
            #pragma unroll
            for (int q = 0; q < 4; q++) {
                uint32_t res = 0;
                #pragma unroll
                for (int b = 0; b < 4; b++) {
                    int gv = (gp[q] >> (8 * b)) & 0xFF;
                    int uv = (int)(int8_t)((up[q] >> (8 * b)) & 0xFF);
                    res |= (uint32_t)((gv * uv) & 0xFF) << (8 * b);
                }
                rp[q] = res;
            }
            *(uint4*)(g_prod8 + off) = r;
        }
        __threadfence();
        __syncthreads();
        if (tid == 0) atomicAdd(&g_sync.row_cnt[m0 >> 7], 1);

    } else {
        // ======== down phase ========
        const int t = bid - N_GATE - N_UP;
        const int m0 = (t >> 5) << 7;
        const int n0 = (t & 31) << 7;

        wait_flag(&g_sync.wd_ready, 1);          // wd8 packed
        wait_flag(&g_sync.row_cnt[m0 >> 7], 86); // prod8 row-block complete

        int c[4][4][4];
        #pragma unroll
        for (int i = 0; i < 4; i++)
            #pragma unroll
            for (int j = 0; j < 4; j++)
                #pragma unroll
                for (int q = 0; q < 4; q++) c[i][j][q] = 0;

        GEMM_MAINLOOP(tmA, tmW, m0, n0, (F_DIM / 128))

        __syncthreads();
        const float ad = *sad;
        float bb[4][2];
        #pragma unroll
        for (int nf = 0; nf < 4; nf++) {
            int h = n0 + wn * 32 + nf * 8 + 2 * (lane & 3);
            bb[nf][0] = bias[h];
            bb[nf][1] = bias[h + 1];
        }
        float* sf = (float*)smA;
        #pragma unroll
        for (int mf = 0; mf < 4; mf++)
            #pragma unroll
            for (int nf = 0; nf < 4; nf++) {
                int col = wn * 32 + nf * 8 + 2 * (lane & 3);
                int r0 = wm * 64 + mf * 16 + (lane >> 2);
                #pragma unroll
                for (int h = 0; h < 2; h++) {
                    int row = r0 + h * 8;
                    float2 v;
                    v.x = __fadd_rn(__fmul_rn(ad, (float)c[mf][nf][h * 2 + 0]), bb[nf][0]);
                    v.y = __fadd_rn(__fmul_rn(ad, (float)c[mf][nf][h * 2 + 1]), bb[nf][1]);
                    *(float2*)(sf + row * 128 + col) = v;
                }
            }
        __syncthreads();
        const float4* s4 = (const float4*)smA;
        #pragma unroll
        for (int i = 0; i < 16; i++) {
            int lin = i * 256 + tid;
            int row = lin >> 5, ch = lin & 31;
            *(float4*)(out + (size_t)(m0 + row) * H_DIM + n0 + ch * 4) = s4[lin];
        }
    }
}

// ---------------- host ----------------
typedef CUresult (*EncodeFn)(CUtensorMap*, CUtensorMapDataType, cuuint32_t, void*,
                             const cuuint64_t*, const cuuint64_t*, const cuuint32_t*,
                             const cuuint32_t*, CUtensorMapInterleave, CUtensorMapSwizzle,
                             CUtensorMapL2promotion, CUtensorMapFloatOOBfill);

static EncodeFn get_encoder() {
    static EncodeFn fn = nullptr;
    if (!fn) {
        cudaDriverEntryPointQueryResult st;
        void* p = nullptr;
        cudaGetDriverEntryPoint("cuTensorMapEncodeTiled", &p, cudaEnableDefault, &st);
        fn = (EncodeFn)p;
    }
    return fn;
}

static void make_tm_i8(CUtensorMap* tm, void* ptr, uint64_t d0, uint64_t d1) {
    cuuint64_t dims[2] = {d0, d1};
    cuuint64_t strides[1] = {d0};
    cuuint32_t box[2] = {128, 128};
    cuuint32_t es[2] = {1, 1};
    get_encoder()(tm, CU_TENSOR_MAP_DATA_TYPE_UINT8, 2, ptr, dims, strides, box, es,
                  CU_TENSOR_MAP_INTERLEAVE_NONE, CU_TENSOR_MAP_SWIZZLE_128B,
                  CU_TENSOR_MAP_L2_PROMOTION_L2_128B, CU_TENSOR_MAP_FLOAT_OOB_FILL_NONE);
}

extern "C" void kernel_launch(void* const* d_in, const int* in_sizes, int n_in,
                              void* d_out, int out_size) {
    (void)out_size;
    int idxX = -1, idxBias = -1;
    int idxW[4]; int nW = 0;
    int idxB[4]; int nB = 0;
    int idxS[8]; int nS = 0;
    for (int i = 0; i < n_in; i++) {
        long long s = in_sizes[i];
        if (s == (long long)M_TOK * H_DIM)      idxX = i;
        else if (s == (long long)F_DIM * H_DIM) { if (nW < 4) idxW[nW++] = i; }
        else if (s == F_DIM)                    { if (nB < 4) idxB[nB++] = i; }
        else if (s == H_DIM)                    idxBias = i;
        else if (s == 1)                        { if (nS < 8) idxS[nS++] = i; }
    }
    const bool dict_like = (idxX >= 0 && nW == 3 && idxX < idxW[0]);

    const int4* X32  = (const int4*)d_in[idxX];
    const int4* Wg32 = (const int4*)d_in[dict_like ? idxW[0] : idxW[1]];
    const int4* Wu32 = (const int4*)d_in[dict_like ? idxW[1] : idxW[2]];
    const int4* Wd32 = (const int4*)d_in[dict_like ? idxW[2] : idxW[0]];
    const int* bg = (const int*)d_in[idxB[0]];
    const int* bu = (const int*)d_in[idxB[1]];
    const float* b_d = (const float*)d_in[idxBias];
    const float *a_g, *b_g, *a_u, *b_u, *a_d;
    if (dict_like) {
        a_g = (const float*)d_in[idxS[0]];
        b_g = (const float*)d_in[idxS[1]];
        a_u = (const float*)d_in[idxS[2]];
        b_u = (const float*)d_in[idxS[3]];
        a_d = (const float*)d_in[idxS[4]];
    } else {
        a_d = (const float*)d_in[idxS[0]];
        a_g = (const float*)d_in[idxS[1]];
        a_u = (const float*)d_in[idxS[2]];
        b_g = (const float*)d_in[idxS[3]];
        b_u = (const float*)d_in[idxS[4]];
    }
    float* out = (float*)d_out;

    void *x8, *wg8, *wu8, *wd8, *prod, *syncp;
    cudaGetSymbolAddress(&x8,  g_x8);
    cudaGetSymbolAddress(&wg8, g_wg8);
    cudaGetSymbolAddress(&wu8, g_wu8);
    cudaGetSymbolAddress(&wd8, g_wd8);
    cudaGetSymbolAddress(&prod, g_prod8);
    cudaGetSymbolAddress(&syncp, g_sync);

    CUtensorMap tmX, tmG, tmU, tmA, tmW;
    make_tm_i8(&tmX, x8,   H_DIM, M_TOK);
    make_tm_i8(&tmG, wg8,  H_DIM, F_DIM);
    make_tm_i8(&tmU, wu8,  H_DIM, F_DIM);
    make_tm_i8(&tmA, prod, F_DIM, M_TOK);
    make_tm_i8(&tmW, wd8,  F_DIM, H_DIM);

    cudaFuncSetAttribute(k_mega, cudaFuncAttributeMaxDynamicSharedMemorySize, SMEMP);

    static cudaStream_t s1 = nullptr, s2 = nullptr;
    static cudaEvent_t eZ = nullptr, eWu = nullptr, eWd = nullptr;
    if (!s1) {
        cudaStreamCreateWithFlags(&s1, cudaStreamNonBlocking);
        cudaStreamCreateWithFlags(&s2, cudaStreamNonBlocking);
        cudaEventCreateWithFlags(&eZ,  cudaEventDisableTiming);
        cudaEventCreateWithFlags(&eWu, cudaEventDisableTiming);
        cudaEventCreateWithFlags(&eWd, cudaEventDisableTiming);
    }

    const int n4x = (M_TOK * H_DIM) / 4;
    const int n4w = (F_DIM * H_DIM) / 4;

    // zero sync state (per launch; replayed in graph)
    cudaMemsetAsync(syncp, 0, sizeof(SyncState), 0);
    cudaEventRecord(eZ, 0);
    cudaStreamWaitEvent(s1, eZ, 0);
    cudaStreamWaitEvent(s2, eZ, 0);
    // throttled side packs (grid-stride, 296 CTAs) publish ready flags
    k_pack_side<<<296, 256, 0, s1>>>(Wu32, (uint32_t*)wu8, n4w, 0);
    cudaEventRecord(eWu, s1);
    k_pack_side<<<296, 256, 0, s2>>>(Wd32, (uint32_t*)wd8, n4w, 1);
    cudaEventRecord(eWd, s2);
    // critical path: pack X+Wg, then the fused 3-GEMM mega kernel
    k_pack_xg<<<((n4x + n4w) / 2 + 255) / 256, 256>>>(X32, Wg32, (uint32_t*)x8, (uint32_t*)wg8, n4x, n4w);
    k_mega<<<N_GATE + N_UP + N_DOWN, 256, SMEMP>>>(
        tmX, tmG, tmU, tmA, tmW, bg, bu, a_g, b_g, a_u, b_u, a_d, b_d, out);
    // join side streams (graph fork-join closure)
    cudaStreamWaitEvent(0, eWu, 0);
    cudaStreamWaitEvent(0, eWd, 0);
}